// round 7
// baseline (speedup 1.0000x reference)
#include <cuda_runtime.h>
#include <cuda_fp16.h>

// NATSearch: 2D neighborhood attention (NATTEN-style).
// prep (fp16 convert/transpose of x and w_qkv) -> qkv GEMM on tensor cores
// -> per-head neighborhood attention (fp16 k/v smem, fp32 softmax) -> proj GEMM.

#define NIMG   4
#define HW     64
#define CCH    64
#define NHEADS 2
#define DHEAD  32
#define KWIN   7
#define NPIX   (NIMG * HW * HW)   // 16384
#define QKVD   192
#define NBDIM  14
#define NNB    (NBDIM * NBDIM)    // 196
#define APITCH 40                 // attn smem pitch in halfs (80B, 16B-aligned rows)
#define XPITCH 72                 // qkv smem pitch in halfs (144B, ldmatrix conflict-free)
#define QSCALE 0.17677669529663687f  // 32^-0.5

__device__ __align__(16) __half g_xh[NPIX * CCH];   // [pix][c] fp16 input
__device__ __align__(16) __half g_wh[QKVD * CCH];   // [j][c]  fp16 w_qkv^T
__device__ __align__(16) float  g_q [NPIX * CCH];   // [pix][64] fp32 (pre-scaled)
__device__ __align__(16) __half g_kh[NPIX * CCH];   // [pix][64] fp16
__device__ __align__(16) __half g_vh[NPIX * CCH];   // [pix][64] fp16
__device__ __align__(16) float  g_att[CCH * NPIX];  // c-major [c][pix]

// ---------------------------------------------------------------------------
// mma.sync / ldmatrix helpers
// ---------------------------------------------------------------------------
__device__ __forceinline__ void ldsm4(unsigned r[4], unsigned addr) {
    asm volatile("ldmatrix.sync.aligned.m8n8.x4.shared.b16 {%0,%1,%2,%3}, [%4];"
                 : "=r"(r[0]), "=r"(r[1]), "=r"(r[2]), "=r"(r[3]) : "r"(addr));
}
__device__ __forceinline__ void ldsm2(unsigned r[2], unsigned addr) {
    asm volatile("ldmatrix.sync.aligned.m8n8.x2.shared.b16 {%0,%1}, [%2];"
                 : "=r"(r[0]), "=r"(r[1]) : "r"(addr));
}
__device__ __forceinline__ void mma16816(float c[4], const unsigned a[4], const unsigned b[2]) {
    asm volatile(
        "mma.sync.aligned.m16n8k16.row.col.f32.f16.f16.f32 "
        "{%0,%1,%2,%3},{%4,%5,%6,%7},{%8,%9},{%0,%1,%2,%3};"
        : "+f"(c[0]), "+f"(c[1]), "+f"(c[2]), "+f"(c[3])
        : "r"(a[0]), "r"(a[1]), "r"(a[2]), "r"(a[3]), "r"(b[0]), "r"(b[1]));
}

// ---------------------------------------------------------------------------
// Kernel 0: prep. Blocks 0..255: transpose-convert vid -> g_xh[pix][c].
// Block 256: convert w_qkv[c][j] -> g_wh[j][c].
// ---------------------------------------------------------------------------
__global__ void __launch_bounds__(256) prep_kernel(const float* __restrict__ vid,
                                                   const float* __restrict__ w_qkv) {
    const int b   = blockIdx.x;
    const int tid = threadIdx.x;
    if (b < 256) {
        __shared__ __half xs[64][XPITCH];
        const float* vbase = vid + (b >> 6) * 262144 + (b & 63) * 64;  // n, x-row
        for (int i = tid; i < 4096; i += 256) {
            const int c = i >> 6, y = i & 63;
            xs[y][c] = __float2half(vbase[c * 4096 + y]);
        }
        __syncthreads();
        for (int i = tid; i < 512; i += 256) {
            const int y = i >> 3, seg = i & 7;
            *(uint4*)(g_xh + (size_t)(b * 64 + y) * 64 + seg * 8) = *(const uint4*)&xs[y][seg * 8];
        }
    } else {
        for (int i = tid; i < 64 * QKVD; i += 256) {
            const int c = i / QKVD, j = i % QKVD;
            g_wh[j * 64 + c] = __float2half(w_qkv[i]);
        }
    }
}

// ---------------------------------------------------------------------------
// Kernel 1: qkv = x @ w_qkv + b_qkv on tensor cores.
// 256 thr / 8 warps, tile 64 px x 192 cols; warp w: cols [24w, 24w+24).
// Staging = pure uint4 copies of pre-converted fp16 planes.
// ---------------------------------------------------------------------------
__global__ void __launch_bounds__(256) qkv_tc_kernel(const float* __restrict__ b_qkv) {
    __shared__ __half xh[64 * XPITCH];    // [px][c]
    __shared__ __half wh[QKVD * XPITCH];  // [j][c]

    const int tid  = threadIdx.x;
    const int lane = tid & 31;
    const int warp = tid >> 5;
    const int pix0 = blockIdx.x * 64;

    for (int i = tid; i < 512; i += 256) {          // x: 64 px x 8 seg
        const int px = i >> 3, seg = i & 7;
        *(uint4*)&xh[px * XPITCH + seg * 8] = *(const uint4*)(g_xh + (size_t)(pix0 + px) * 64 + seg * 8);
    }
    for (int i = tid; i < 1536; i += 256) {         // w: 192 j x 8 seg
        const int j = i >> 3, seg = i & 7;
        *(uint4*)&wh[j * XPITCH + seg * 8] = *(const uint4*)(g_wh + j * 64 + seg * 8);
    }
    __syncthreads();

    const unsigned xbase = (unsigned)__cvta_generic_to_shared(xh);
    const unsigned wbase = (unsigned)__cvta_generic_to_shared(wh);
    const int wn0 = warp * 24;
    const int arow = lane & 15;
    const int acol8 = ((lane >> 4) & 1) * 8;
    const int l16 = lane & 15;

#pragma unroll
    for (int nt = 0; nt < 3; nt++) {
        float acc[4][4];
#pragma unroll
        for (int mt = 0; mt < 4; mt++)
#pragma unroll
            for (int r = 0; r < 4; r++) acc[mt][r] = 0.f;

#pragma unroll
        for (int ks = 0; ks < 4; ks++) {
            unsigned bfr[2];
            {
                const int brow = wn0 + nt * 8 + (l16 & 7);
                const int bcol = ks * 16 + ((l16 >> 3) & 1) * 8;
                ldsm2(bfr, wbase + (unsigned)(brow * XPITCH + bcol) * 2u);
            }
#pragma unroll
            for (int mt = 0; mt < 4; mt++) {
                unsigned afr[4];
                const int row = mt * 16 + arow;
                const int col = ks * 16 + acol8;
                ldsm4(afr, xbase + (unsigned)(row * XPITCH + col) * 2u);
                mma16816(acc[mt], afr, bfr);
            }
        }

        const int J = wn0 + nt * 8 + 2 * (lane & 3);
        const float b0 = b_qkv[J], b1 = b_qkv[J + 1];
#pragma unroll
        for (int mt = 0; mt < 4; mt++) {
            const int pxa = pix0 + mt * 16 + (lane >> 2);
            const int pxb = pxa + 8;
            if (J < 64) {
                float2 r0 = make_float2((acc[mt][0] + b0) * QSCALE, (acc[mt][1] + b1) * QSCALE);
                float2 r1 = make_float2((acc[mt][2] + b0) * QSCALE, (acc[mt][3] + b1) * QSCALE);
                *(float2*)(g_q + (size_t)pxa * 64 + J) = r0;
                *(float2*)(g_q + (size_t)pxb * 64 + J) = r1;
            } else if (J < 128) {
                const int off = J - 64;
                *(__half2*)(g_kh + (size_t)pxa * 64 + off) = __floats2half2_rn(acc[mt][0] + b0, acc[mt][1] + b1);
                *(__half2*)(g_kh + (size_t)pxb * 64 + off) = __floats2half2_rn(acc[mt][2] + b0, acc[mt][3] + b1);
            } else {
                const int off = J - 128;
                *(__half2*)(g_vh + (size_t)pxa * 64 + off) = __floats2half2_rn(acc[mt][0] + b0, acc[mt][1] + b1);
                *(__half2*)(g_vh + (size_t)pxb * 64 + off) = __floats2half2_rn(acc[mt][2] + b0, acc[mt][3] + b1);
            }
        }
    }
}

// ---------------------------------------------------------------------------
// Kernel 2: neighborhood attention, ONE HEAD per block. Grid (64,2,4),
// 64 threads = 64 queries. k/v 14x14 nb (32ch for this head) fp16 in smem.
// ---------------------------------------------------------------------------
__global__ void __launch_bounds__(64) attn_kernel(const float* __restrict__ rpb) {
    extern __shared__ char smraw[];
    __half* ks = (__half*)smraw;                  // [196][APITCH]
    __half* vs = ks + NNB * APITCH;               // [196][APITCH]
    float*  rs = (float*)(vs + NNB * APITCH);     // [169]

    const int tid  = threadIdx.x;
    const int head = blockIdx.y;
    const int n    = blockIdx.z;
    const int x0   = (blockIdx.x >> 3) * 8;
    const int y0   = (blockIdx.x & 7) * 8;
    const int rb   = min(max(x0 - 3, 0), 50);
    const int cb   = min(max(y0 - 3, 0), 50);

    const int qx = tid >> 3, qy = tid & 7;
    const int xx = x0 + qx, yy = y0 + qy;
    const int hb = head * DHEAD;
    const int pix = n * 4096 + xx * 64 + yy;

    float q[32];
    {
        const float* qp = g_q + (size_t)pix * 64 + hb;
#pragma unroll
        for (int dq = 0; dq < 8; dq++) {
            const float4 t = *(const float4*)(qp + dq * 4);
            q[dq * 4 + 0] = t.x; q[dq * 4 + 1] = t.y;
            q[dq * 4 + 2] = t.z; q[dq * 4 + 3] = t.w;
        }
    }

    // stage k/v: 196 nb pixels x 8 uint4 (4 k + 4 v), 32 halfs per plane
    for (int i = tid; i < NNB * 8; i += 64) {
        const int nb = i >> 3, part = i & 7;
        const int gr = rb + nb / NBDIM, gc = cb + nb % NBDIM;
        const size_t ps = (size_t)(n * 4096 + gr * 64 + gc) * 64 + hb;
        if (part < 4)
            *(uint4*)(ks + nb * APITCH + part * 8) = *(const uint4*)(g_kh + ps + part * 8);
        else
            *(uint4*)(vs + nb * APITCH + (part - 4) * 8) = *(const uint4*)(g_vh + ps + (part - 4) * 8);
    }
    for (int i = tid; i < 169; i += 64) rs[i] = rpb[head * 169 + i];
    __syncthreads();

    const int sx = min(max(xx - 3, 0), 57), sy = min(max(yy - 3, 0), 57);
    const int r0 = sx - rb, c0 = sy - cb;
    const int bh = sx - xx + 6, bw = sy - yy + 6;

    float lg[49];
#pragma unroll
    for (int a = 0; a < KWIN; a++) {
#pragma unroll
        for (int b = 0; b < KWIN; b++) {
            const __half* kp = ks + ((r0 + a) * NBDIM + c0 + b) * APITCH;
            float a0 = 0.f, a1 = 0.f, a2 = 0.f, a3 = 0.f;
#pragma unroll
            for (int u = 0; u < 4; u++) {
                const uint4 r = *(const uint4*)(kp + u * 8);
                const float2 f0 = __half22float2(*(const __half2*)&r.x);
                const float2 f1 = __half22float2(*(const __half2*)&r.y);
                const float2 f2 = __half22float2(*(const __half2*)&r.z);
                const float2 f3 = __half22float2(*(const __half2*)&r.w);
                a0 += q[u * 8 + 0] * f0.x + q[u * 8 + 4] * f2.x;
                a1 += q[u * 8 + 1] * f0.y + q[u * 8 + 5] * f2.y;
                a2 += q[u * 8 + 2] * f1.x + q[u * 8 + 6] * f3.x;
                a3 += q[u * 8 + 3] * f1.y + q[u * 8 + 7] * f3.y;
            }
            lg[a * KWIN + b] = (a0 + a1) + (a2 + a3) + rs[(bh + a) * 13 + bw + b];
        }
    }

    float m = lg[0];
#pragma unroll
    for (int i = 1; i < 49; i++) m = fmaxf(m, lg[i]);
    float s = 0.f;
#pragma unroll
    for (int i = 0; i < 49; i++) { const float e = __expf(lg[i] - m); lg[i] = e; s += e; }
    const float inv = 1.0f / s;

    float o[32];
#pragma unroll
    for (int d = 0; d < 32; d++) o[d] = 0.f;
#pragma unroll
    for (int a = 0; a < KWIN; a++) {
#pragma unroll
        for (int b = 0; b < KWIN; b++) {
            const float w = lg[a * KWIN + b];
            const __half* vp = vs + ((r0 + a) * NBDIM + c0 + b) * APITCH;
#pragma unroll
            for (int u = 0; u < 4; u++) {
                const uint4 r = *(const uint4*)(vp + u * 8);
                const float2 f0 = __half22float2(*(const __half2*)&r.x);
                const float2 f1 = __half22float2(*(const __half2*)&r.y);
                const float2 f2 = __half22float2(*(const __half2*)&r.z);
                const float2 f3 = __half22float2(*(const __half2*)&r.w);
                o[u * 8 + 0] += w * f0.x; o[u * 8 + 1] += w * f0.y;
                o[u * 8 + 2] += w * f1.x; o[u * 8 + 3] += w * f1.y;
                o[u * 8 + 4] += w * f2.x; o[u * 8 + 5] += w * f2.y;
                o[u * 8 + 6] += w * f3.x; o[u * 8 + 7] += w * f3.y;
            }
        }
    }

#pragma unroll
    for (int d = 0; d < 32; d++) g_att[(size_t)(hb + d) * NPIX + pix] = o[d] * inv;
}

// ---------------------------------------------------------------------------
// Kernel 3: out = attn @ w_proj + b_proj (unchanged, passing).
// ---------------------------------------------------------------------------
__global__ void __launch_bounds__(256) proj_kernel(const float* __restrict__ w_proj,
                                                   const float* __restrict__ b_proj,
                                                   float* __restrict__ out, int out_size) {
    __shared__ float xs[64][64];
    const int tid  = threadIdx.x;
    const int pix0 = blockIdx.x * 64;

    for (int i = tid; i < 1024; i += 256) {
        const int c = i >> 4, qq = i & 15;
        *(float4*)&xs[c][qq * 4] = *(const float4*)(g_att + (size_t)c * NPIX + pix0 + qq * 4);
    }
    __syncthreads();

    const int pg = tid >> 4, jg = tid & 15;
    const int px0 = pg * 4, j0 = jg * 4;

    float acc[4][4];
#pragma unroll
    for (int p = 0; p < 4; p++)
#pragma unroll
        for (int j = 0; j < 4; j++) acc[p][j] = 0.f;

#pragma unroll 8
    for (int c = 0; c < 64; c++) {
        const float4 xa = *(const float4*)&xs[c][px0];
        const float4 wa = *(const float4*)(w_proj + c * 64 + j0);
        const float xv[4] = {xa.x, xa.y, xa.z, xa.w};
        const float wv[4] = {wa.x, wa.y, wa.z, wa.w};
#pragma unroll
        for (int p = 0; p < 4; p++)
#pragma unroll
            for (int j = 0; j < 4; j++) acc[p][j] += xv[p] * wv[j];
    }

    const float4 b4 = *(const float4*)(b_proj + j0);
#pragma unroll
    for (int p = 0; p < 4; p++) {
        float4 r;
        r.x = acc[p][0] + b4.x; r.y = acc[p][1] + b4.y;
        r.z = acc[p][2] + b4.z; r.w = acc[p][3] + b4.w;
        *(float4*)(out + (size_t)(pix0 + px0 + p) * 64 + j0) = r;
    }

    if (blockIdx.x == 0) {
        for (int i = NPIX * CCH + tid; i < out_size; i += 256) out[i] = 0.0f;
    }
}

// ---------------------------------------------------------------------------
extern "C" void kernel_launch(void* const* d_in, const int* in_sizes, int n_in,
                              void* d_out, int out_size) {
    const float* vid    = (const float*)d_in[0];
    const float* w_qkv  = (const float*)d_in[4];
    const float* b_qkv  = (const float*)d_in[5];
    const float* rpb    = (const float*)d_in[6];
    const float* w_proj = (const float*)d_in[7];
    const float* b_proj = (const float*)d_in[8];
    float* out = (float*)d_out;

    prep_kernel<<<257, 256>>>(vid, w_qkv);
    qkv_tc_kernel<<<NPIX / 64, 256>>>(b_qkv);

    const int attn_smem = 2 * NNB * APITCH * (int)sizeof(__half) + 169 * (int)sizeof(float);
    cudaFuncSetAttribute(attn_kernel, cudaFuncAttributeMaxDynamicSharedMemorySize, attn_smem);
    attn_kernel<<<dim3(64, NHEADS, NIMG), 64, attn_smem>>>(rpb);

    proj_kernel<<<NPIX / 64, 256>>>(w_proj, b_proj, out, out_size);
}

// round 8
// speedup vs baseline: 1.4952x; 1.4952x over previous
#include <cuda_runtime.h>
#include <cuda_fp16.h>

// NATSearch: 2D neighborhood attention (NATTEN-style).
// wprep (fp16 w_qkv^T) -> qkv GEMM TC (local x convert) ->
// per-head attention, 2 threads/query -> proj GEMM TC.

#define NIMG   4
#define HW     64
#define CCH    64
#define NHEADS 2
#define DHEAD  32
#define KWIN   7
#define NPIX   (NIMG * HW * HW)   // 16384
#define QKVD   192
#define NBDIM  14
#define NNB    (NBDIM * NBDIM)    // 196
#define APITCH 40                 // attn smem pitch in halfs
#define XPITCH 72                 // mma smem pitch in halfs (144B rows)
#define QSCALE 0.17677669529663687f

__device__ __align__(16) __half g_wh[QKVD * CCH];   // [j][c] fp16 w_qkv^T
__device__ __align__(16) float  g_q [NPIX * CCH];   // [pix][64] fp32 (pre-scaled)
__device__ __align__(16) __half g_kh[NPIX * CCH];   // [pix][64] fp16
__device__ __align__(16) __half g_vh[NPIX * CCH];   // [pix][64] fp16
__device__ __align__(16) float  g_att[CCH * NPIX];  // c-major [c][pix] fp32

// ---------------------------------------------------------------------------
__device__ __forceinline__ void ldsm4(unsigned r[4], unsigned addr) {
    asm volatile("ldmatrix.sync.aligned.m8n8.x4.shared.b16 {%0,%1,%2,%3}, [%4];"
                 : "=r"(r[0]), "=r"(r[1]), "=r"(r[2]), "=r"(r[3]) : "r"(addr));
}
__device__ __forceinline__ void ldsm2(unsigned r[2], unsigned addr) {
    asm volatile("ldmatrix.sync.aligned.m8n8.x2.shared.b16 {%0,%1}, [%2];"
                 : "=r"(r[0]), "=r"(r[1]) : "r"(addr));
}
__device__ __forceinline__ void mma16816(float c[4], const unsigned a[4], const unsigned b[2]) {
    asm volatile(
        "mma.sync.aligned.m16n8k16.row.col.f32.f16.f16.f32 "
        "{%0,%1,%2,%3},{%4,%5,%6,%7},{%8,%9},{%0,%1,%2,%3};"
        : "+f"(c[0]), "+f"(c[1]), "+f"(c[2]), "+f"(c[3])
        : "r"(a[0]), "r"(a[1]), "r"(a[2]), "r"(a[3]), "r"(b[0]), "r"(b[1]));
}

// ---------------------------------------------------------------------------
// Kernel 0: w_qkv[c][j] -> g_wh[j][c] fp16. 12288 threads, 1 elem each.
// ---------------------------------------------------------------------------
__global__ void __launch_bounds__(256) wprep_kernel(const float* __restrict__ w_qkv) {
    const int t = blockIdx.x * 256 + threadIdx.x;      // 0..12287
    const int c = t / QKVD, j = t - c * QKVD;
    g_wh[j * 64 + c] = __float2half(w_qkv[t]);
}

// ---------------------------------------------------------------------------
// Kernel 1: qkv = x @ w_qkv + b_qkv (tensor cores). 256 thr / 8 warps,
// tile 64 px x 192 cols; warp w covers cols [24w,24w+24).
// x-tile converted locally; wh copied from pre-converted g_wh.
// ---------------------------------------------------------------------------
__global__ void __launch_bounds__(256) qkv_tc_kernel(const float* __restrict__ vid,
                                                     const float* __restrict__ b_qkv) {
    __shared__ __half xh[64 * XPITCH];    // [px][c]
    __shared__ __half wh[QKVD * XPITCH];  // [j][c]

    const int tid  = threadIdx.x;
    const int lane = tid & 31;
    const int warp = tid >> 5;
    const int pix0 = blockIdx.x * 64;
    const int n  = pix0 >> 12;
    const int xr = (pix0 >> 6) & 63;
    const float* vbase = vid + n * 262144 + xr * 64;

#pragma unroll
    for (int it = 0; it < 16; it++) {               // x: convert + transpose
        const int i = tid + it * 256;               // 0..4095
        const int c = i >> 6, y = i & 63;
        xh[y * XPITCH + c] = __float2half(vbase[c * 4096 + y]);
    }
#pragma unroll
    for (int it = 0; it < 6; it++) {                // w: uint4 copy
        const int i = tid + it * 256;               // 0..1535
        const int j = i >> 3, seg = i & 7;
        *(uint4*)&wh[j * XPITCH + seg * 8] = *(const uint4*)(g_wh + j * 64 + seg * 8);
    }
    __syncthreads();

    const unsigned xbase = (unsigned)__cvta_generic_to_shared(xh);
    const unsigned wbase = (unsigned)__cvta_generic_to_shared(wh);
    const int wn0 = warp * 24;
    const int arow = lane & 15;
    const int acol8 = ((lane >> 4) & 1) * 8;
    const int l16 = lane & 15;

#pragma unroll
    for (int nt = 0; nt < 3; nt++) {
        float acc[4][4];
#pragma unroll
        for (int mt = 0; mt < 4; mt++)
#pragma unroll
            for (int r = 0; r < 4; r++) acc[mt][r] = 0.f;

#pragma unroll
        for (int ks = 0; ks < 4; ks++) {
            unsigned bfr[2];
            {
                const int brow = wn0 + nt * 8 + (l16 & 7);
                const int bcol = ks * 16 + ((l16 >> 3) & 1) * 8;
                ldsm2(bfr, wbase + (unsigned)(brow * XPITCH + bcol) * 2u);
            }
#pragma unroll
            for (int mt = 0; mt < 4; mt++) {
                unsigned afr[4];
                const int row = mt * 16 + arow;
                const int col = ks * 16 + acol8;
                ldsm4(afr, xbase + (unsigned)(row * XPITCH + col) * 2u);
                mma16816(acc[mt], afr, bfr);
            }
        }

        const int J = wn0 + nt * 8 + 2 * (lane & 3);
        const float b0 = b_qkv[J], b1 = b_qkv[J + 1];
#pragma unroll
        for (int mt = 0; mt < 4; mt++) {
            const int pxa = pix0 + mt * 16 + (lane >> 2);
            const int pxb = pxa + 8;
            if (J < 64) {
                float2 r0 = make_float2((acc[mt][0] + b0) * QSCALE, (acc[mt][1] + b1) * QSCALE);
                float2 r1 = make_float2((acc[mt][2] + b0) * QSCALE, (acc[mt][3] + b1) * QSCALE);
                *(float2*)(g_q + (size_t)pxa * 64 + J) = r0;
                *(float2*)(g_q + (size_t)pxb * 64 + J) = r1;
            } else if (J < 128) {
                const int off = J - 64;
                *(__half2*)(g_kh + (size_t)pxa * 64 + off) = __floats2half2_rn(acc[mt][0] + b0, acc[mt][1] + b1);
                *(__half2*)(g_kh + (size_t)pxb * 64 + off) = __floats2half2_rn(acc[mt][2] + b0, acc[mt][3] + b1);
            } else {
                const int off = J - 128;
                *(__half2*)(g_vh + (size_t)pxa * 64 + off) = __floats2half2_rn(acc[mt][0] + b0, acc[mt][1] + b1);
                *(__half2*)(g_vh + (size_t)pxb * 64 + off) = __floats2half2_rn(acc[mt][2] + b0, acc[mt][3] + b1);
            }
        }
    }
}

// ---------------------------------------------------------------------------
// Kernel 2: attention, one head per block, TWO threads per query.
// 128 thr: half = tid>>6 handles window positions [25h, 25h+25-h).
// ---------------------------------------------------------------------------
__global__ void __launch_bounds__(128) attn_kernel(const float* __restrict__ rpb) {
    __shared__ __half ks[NNB * APITCH];
    __shared__ __half vs[NNB * APITCH];
    __shared__ float  rs[169];
    __shared__ float  pm[128];
    __shared__ float  ps[128];
    __shared__ float  os[64][33];

    const int tid  = threadIdx.x;
    const int half = tid >> 6;
    const int qid  = tid & 63;
    const int head = blockIdx.y;
    const int n    = blockIdx.z;
    const int x0   = (blockIdx.x >> 3) * 8;
    const int y0   = (blockIdx.x & 7) * 8;
    const int rb   = min(max(x0 - 3, 0), 50);
    const int cb   = min(max(y0 - 3, 0), 50);

    const int qx = qid >> 3, qy = qid & 7;
    const int xx = x0 + qx, yy = y0 + qy;
    const int hb = head * DHEAD;
    const int pix = n * 4096 + xx * 64 + yy;

    float q[32];
    {
        const float* qp = g_q + (size_t)pix * 64 + hb;
#pragma unroll
        for (int dq = 0; dq < 8; dq++) {
            const float4 t = *(const float4*)(qp + dq * 4);
            q[dq * 4 + 0] = t.x; q[dq * 4 + 1] = t.y;
            q[dq * 4 + 2] = t.z; q[dq * 4 + 3] = t.w;
        }
    }

    for (int i = tid; i < NNB * 8; i += 128) {
        const int nb = i >> 3, part = i & 7;
        const int gr = rb + nb / NBDIM, gc = cb + nb % NBDIM;
        const size_t psrc = (size_t)(n * 4096 + gr * 64 + gc) * 64 + hb;
        if (part < 4)
            *(uint4*)(ks + nb * APITCH + part * 8) = *(const uint4*)(g_kh + psrc + part * 8);
        else
            *(uint4*)(vs + nb * APITCH + (part - 4) * 8) = *(const uint4*)(g_vh + psrc + (part - 4) * 8);
    }
    for (int i = tid; i < 169; i += 128) rs[i] = rpb[head * 169 + i];
    __syncthreads();

    const int sx = min(max(xx - 3, 0), 57), sy = min(max(yy - 3, 0), 57);
    const int r0 = sx - rb, c0 = sy - cb;
    const int bh = sx - xx + 6, bw = sy - yy + 6;

    const int pbase = half * 25;
    const int pcnt  = 25 - half;     // 25 for half0, 24 for half1

    float lg[25];
    float m = -1e30f;
#pragma unroll
    for (int pp = 0; pp < 25; pp++) {
        if (pp < pcnt) {
            const int p = pbase + pp;
            const int a = p / 7, b = p % 7;
            const __half* kp = ks + ((r0 + a) * NBDIM + c0 + b) * APITCH;
            float a0 = 0.f, a1 = 0.f, a2 = 0.f, a3 = 0.f;
#pragma unroll
            for (int u = 0; u < 4; u++) {
                const uint4 r = *(const uint4*)(kp + u * 8);
                const float2 f0 = __half22float2(*(const __half2*)&r.x);
                const float2 f1 = __half22float2(*(const __half2*)&r.y);
                const float2 f2 = __half22float2(*(const __half2*)&r.z);
                const float2 f3 = __half22float2(*(const __half2*)&r.w);
                a0 += q[u * 8 + 0] * f0.x + q[u * 8 + 4] * f2.x;
                a1 += q[u * 8 + 1] * f0.y + q[u * 8 + 5] * f2.y;
                a2 += q[u * 8 + 2] * f1.x + q[u * 8 + 6] * f3.x;
                a3 += q[u * 8 + 3] * f1.y + q[u * 8 + 7] * f3.y;
            }
            lg[pp] = (a0 + a1) + (a2 + a3) + rs[(bh + a) * 13 + bw + b];
            m = fmaxf(m, lg[pp]);
        }
    }

    pm[tid] = m;
    __syncthreads();
    m = fmaxf(pm[qid], pm[qid + 64]);

    float s = 0.f;
#pragma unroll
    for (int pp = 0; pp < 25; pp++) {
        if (pp < pcnt) { const float e = __expf(lg[pp] - m); lg[pp] = e; s += e; }
    }
    ps[tid] = s;
    __syncthreads();
    const float inv = 1.0f / (ps[qid] + ps[qid + 64]);

    float o[32];
#pragma unroll
    for (int d = 0; d < 32; d++) o[d] = 0.f;
#pragma unroll
    for (int pp = 0; pp < 25; pp++) {
        if (pp < pcnt) {
            const int p = pbase + pp;
            const int a = p / 7, b = p % 7;
            const float w = lg[pp];
            const __half* vp = vs + ((r0 + a) * NBDIM + c0 + b) * APITCH;
#pragma unroll
            for (int u = 0; u < 4; u++) {
                const uint4 r = *(const uint4*)(vp + u * 8);
                const float2 f0 = __half22float2(*(const __half2*)&r.x);
                const float2 f1 = __half22float2(*(const __half2*)&r.y);
                const float2 f2 = __half22float2(*(const __half2*)&r.z);
                const float2 f3 = __half22float2(*(const __half2*)&r.w);
                o[u * 8 + 0] += w * f0.x; o[u * 8 + 1] += w * f0.y;
                o[u * 8 + 2] += w * f1.x; o[u * 8 + 3] += w * f1.y;
                o[u * 8 + 4] += w * f2.x; o[u * 8 + 5] += w * f2.y;
                o[u * 8 + 6] += w * f3.x; o[u * 8 + 7] += w * f3.y;
            }
        }
    }

    if (half == 1) {
#pragma unroll
        for (int d = 0; d < 32; d++) os[qid][d] = o[d];
    }
    __syncthreads();
    if (half == 0) {
#pragma unroll
        for (int d = 0; d < 32; d++)
            g_att[(size_t)(hb + d) * NPIX + pix] = (o[d] + os[qid][d]) * inv;
    }
}

// ---------------------------------------------------------------------------
// Kernel 3: proj on tensor cores. 256 thr / 8 warps, tile 64 px x 64 j;
// warp covers 8 j-cols. Stages convert g_att (fp32 c-major) and w_proj to fp16.
// ---------------------------------------------------------------------------
__global__ void __launch_bounds__(256) proj_tc_kernel(const float* __restrict__ w_proj,
                                                      const float* __restrict__ b_proj,
                                                      float* __restrict__ out, int out_size) {
    __shared__ __half xh[64 * XPITCH];   // [px][c]
    __shared__ __half wh[64 * XPITCH];   // [j][c]

    const int tid  = threadIdx.x;
    const int lane = tid & 31;
    const int warp = tid >> 5;
    const int pix0 = blockIdx.x * 64;

#pragma unroll
    for (int it = 0; it < 4; it++) {                 // x: 1024 float4 reads
        const int i = tid + it * 256;
        const int c = i >> 4, q4 = i & 15;
        const float4 t = *(const float4*)(g_att + (size_t)c * NPIX + pix0 + q4 * 4);
        const int px = q4 * 4;
        xh[(px + 0) * XPITCH + c] = __float2half(t.x);
        xh[(px + 1) * XPITCH + c] = __float2half(t.y);
        xh[(px + 2) * XPITCH + c] = __float2half(t.z);
        xh[(px + 3) * XPITCH + c] = __float2half(t.w);
    }
#pragma unroll
    for (int it = 0; it < 16; it++) {                // w: convert + transpose
        const int i = tid + it * 256;                // 0..4095
        const int c = i >> 6, j = i & 63;
        wh[j * XPITCH + c] = __float2half(w_proj[i]);
    }
    __syncthreads();

    const unsigned xbase = (unsigned)__cvta_generic_to_shared(xh);
    const unsigned wbase = (unsigned)__cvta_generic_to_shared(wh);
    const int j0 = warp * 8;
    const int arow = lane & 15;
    const int acol8 = ((lane >> 4) & 1) * 8;
    const int l16 = lane & 15;

    float acc[4][4];
#pragma unroll
    for (int mt = 0; mt < 4; mt++)
#pragma unroll
        for (int r = 0; r < 4; r++) acc[mt][r] = 0.f;

#pragma unroll
    for (int ks = 0; ks < 4; ks++) {
        unsigned bfr[2];
        {
            const int brow = j0 + (l16 & 7);
            const int bcol = ks * 16 + ((l16 >> 3) & 1) * 8;
            ldsm2(bfr, wbase + (unsigned)(brow * XPITCH + bcol) * 2u);
        }
#pragma unroll
        for (int mt = 0; mt < 4; mt++) {
            unsigned afr[4];
            const int row = mt * 16 + arow;
            const int col = ks * 16 + acol8;
            ldsm4(afr, xbase + (unsigned)(row * XPITCH + col) * 2u);
            mma16816(acc[mt], afr, bfr);
        }
    }

    const int J = j0 + 2 * (lane & 3);
    const float b0 = b_proj[J], b1 = b_proj[J + 1];
#pragma unroll
    for (int mt = 0; mt < 4; mt++) {
        const int pxa = pix0 + mt * 16 + (lane >> 2);
        const int pxb = pxa + 8;
        *(float2*)(out + (size_t)pxa * 64 + J) = make_float2(acc[mt][0] + b0, acc[mt][1] + b1);
        *(float2*)(out + (size_t)pxb * 64 + J) = make_float2(acc[mt][2] + b0, acc[mt][3] + b1);
    }

    if (blockIdx.x == 0) {
        for (int i = NPIX * CCH + tid; i < out_size; i += 256) out[i] = 0.0f;
    }
}

// ---------------------------------------------------------------------------
extern "C" void kernel_launch(void* const* d_in, const int* in_sizes, int n_in,
                              void* d_out, int out_size) {
    const float* vid    = (const float*)d_in[0];
    const float* w_qkv  = (const float*)d_in[4];
    const float* b_qkv  = (const float*)d_in[5];
    const float* rpb    = (const float*)d_in[6];
    const float* w_proj = (const float*)d_in[7];
    const float* b_proj = (const float*)d_in[8];
    float* out = (float*)d_out;

    wprep_kernel<<<48, 256>>>(w_qkv);
    qkv_tc_kernel<<<NPIX / 64, 256>>>(vid, b_qkv);
    attn_kernel<<<dim3(64, NHEADS, NIMG), 128>>>(rpb);
    proj_tc_kernel<<<NPIX / 64, 256>>>(w_proj, b_proj, out, out_size);
}

// round 9
// speedup vs baseline: 1.5271x; 1.0214x over previous
#include <cuda_runtime.h>
#include <cuda_fp16.h>

// NATSearch: 2D neighborhood attention (NATTEN-style).
// wprep (fp16 w_qkv^T + w_proj^T) -> qkv GEMM TC -> per-head attention
// (3-way position split, fp16 output) -> proj GEMM TC (pure-copy staging).

#define NIMG   4
#define HW     64
#define CCH    64
#define NHEADS 2
#define DHEAD  32
#define KWIN   7
#define NPIX   (NIMG * HW * HW)   // 16384
#define QKVD   192
#define NBDIM  14
#define NNB    (NBDIM * NBDIM)    // 196
#define APITCH 40                 // attn smem pitch in halfs (80B rows)
#define XPITCH 72                 // mma smem pitch in halfs (144B rows)
#define QSCALE 0.17677669529663687f

__device__ __align__(16) __half g_wh [QKVD * CCH];  // [j][c] fp16 w_qkv^T
__device__ __align__(16) __half g_wph[CCH * CCH];   // [j][c] fp16 w_proj^T
__device__ __align__(16) float  g_q  [NPIX * CCH];  // [pix][64] fp32 (pre-scaled)
__device__ __align__(16) __half g_kh [NPIX * CCH];  // [pix][64] fp16
__device__ __align__(16) __half g_vh [NPIX * CCH];  // [pix][64] fp16
__device__ __align__(16) __half g_atth[NPIX * CCH]; // [pix][64] fp16 attn output

// ---------------------------------------------------------------------------
__device__ __forceinline__ void ldsm4(unsigned r[4], unsigned addr) {
    asm volatile("ldmatrix.sync.aligned.m8n8.x4.shared.b16 {%0,%1,%2,%3}, [%4];"
                 : "=r"(r[0]), "=r"(r[1]), "=r"(r[2]), "=r"(r[3]) : "r"(addr));
}
__device__ __forceinline__ void ldsm2(unsigned r[2], unsigned addr) {
    asm volatile("ldmatrix.sync.aligned.m8n8.x2.shared.b16 {%0,%1}, [%2];"
                 : "=r"(r[0]), "=r"(r[1]) : "r"(addr));
}
__device__ __forceinline__ void mma16816(float c[4], const unsigned a[4], const unsigned b[2]) {
    asm volatile(
        "mma.sync.aligned.m16n8k16.row.col.f32.f16.f16.f32 "
        "{%0,%1,%2,%3},{%4,%5,%6,%7},{%8,%9},{%0,%1,%2,%3};"
        : "+f"(c[0]), "+f"(c[1]), "+f"(c[2]), "+f"(c[3])
        : "r"(a[0]), "r"(a[1]), "r"(a[2]), "r"(a[3]), "r"(b[0]), "r"(b[1]));
}

// ---------------------------------------------------------------------------
// Kernel 0: weight prep. t<12288: w_qkv[c][j]->g_wh[j][c]. Rest: w_proj.
// ---------------------------------------------------------------------------
__global__ void __launch_bounds__(256) wprep_kernel(const float* __restrict__ w_qkv,
                                                    const float* __restrict__ w_proj) {
    const int t = blockIdx.x * 256 + threadIdx.x;      // 0..16383
    if (t < 64 * QKVD) {
        const int c = t / QKVD, j = t - c * QKVD;
        g_wh[j * 64 + c] = __float2half(w_qkv[t]);
    } else {
        const int t2 = t - 64 * QKVD;                  // 0..4095
        const int c = t2 >> 6, j = t2 & 63;
        g_wph[j * 64 + c] = __float2half(w_proj[t2]);
    }
}

// ---------------------------------------------------------------------------
// Kernel 1: qkv = x @ w_qkv + b_qkv (tensor cores). 256 thr / 8 warps,
// tile 64 px x 192 cols; warp w covers cols [24w,24w+24).
// ---------------------------------------------------------------------------
__global__ void __launch_bounds__(256) qkv_tc_kernel(const float* __restrict__ vid,
                                                     const float* __restrict__ b_qkv) {
    __shared__ __half xh[64 * XPITCH];    // [px][c]
    __shared__ __half wh[QKVD * XPITCH];  // [j][c]

    const int tid  = threadIdx.x;
    const int lane = tid & 31;
    const int warp = tid >> 5;
    const int pix0 = blockIdx.x * 64;
    const int n  = pix0 >> 12;
    const int xr = (pix0 >> 6) & 63;
    const float* vbase = vid + n * 262144 + xr * 64;

#pragma unroll
    for (int it = 0; it < 4; it++) {                // x: float4 load + transpose-convert
        const int i = tid + it * 256;               // 0..1023
        const int c = i >> 4, y4 = (i & 15) * 4;
        const float4 t = *(const float4*)(vbase + c * 4096 + y4);
        xh[(y4 + 0) * XPITCH + c] = __float2half(t.x);
        xh[(y4 + 1) * XPITCH + c] = __float2half(t.y);
        xh[(y4 + 2) * XPITCH + c] = __float2half(t.z);
        xh[(y4 + 3) * XPITCH + c] = __float2half(t.w);
    }
#pragma unroll
    for (int it = 0; it < 6; it++) {                // w: uint4 copy
        const int i = tid + it * 256;               // 0..1535
        const int j = i >> 3, seg = i & 7;
        *(uint4*)&wh[j * XPITCH + seg * 8] = *(const uint4*)(g_wh + j * 64 + seg * 8);
    }
    __syncthreads();

    const unsigned xbase = (unsigned)__cvta_generic_to_shared(xh);
    const unsigned wbase = (unsigned)__cvta_generic_to_shared(wh);
    const int wn0 = warp * 24;
    const int arow = lane & 15;
    const int acol8 = ((lane >> 4) & 1) * 8;
    const int l16 = lane & 15;

#pragma unroll
    for (int nt = 0; nt < 3; nt++) {
        float acc[4][4];
#pragma unroll
        for (int mt = 0; mt < 4; mt++)
#pragma unroll
            for (int r = 0; r < 4; r++) acc[mt][r] = 0.f;

#pragma unroll
        for (int ks = 0; ks < 4; ks++) {
            unsigned bfr[2];
            {
                const int brow = wn0 + nt * 8 + (l16 & 7);
                const int bcol = ks * 16 + ((l16 >> 3) & 1) * 8;
                ldsm2(bfr, wbase + (unsigned)(brow * XPITCH + bcol) * 2u);
            }
#pragma unroll
            for (int mt = 0; mt < 4; mt++) {
                unsigned afr[4];
                const int row = mt * 16 + arow;
                const int col = ks * 16 + acol8;
                ldsm4(afr, xbase + (unsigned)(row * XPITCH + col) * 2u);
                mma16816(acc[mt], afr, bfr);
            }
        }

        const int J = wn0 + nt * 8 + 2 * (lane & 3);
        const float b0 = b_qkv[J], b1 = b_qkv[J + 1];
#pragma unroll
        for (int mt = 0; mt < 4; mt++) {
            const int pxa = pix0 + mt * 16 + (lane >> 2);
            const int pxb = pxa + 8;
            if (J < 64) {
                float2 r0 = make_float2((acc[mt][0] + b0) * QSCALE, (acc[mt][1] + b1) * QSCALE);
                float2 r1 = make_float2((acc[mt][2] + b0) * QSCALE, (acc[mt][3] + b1) * QSCALE);
                *(float2*)(g_q + (size_t)pxa * 64 + J) = r0;
                *(float2*)(g_q + (size_t)pxb * 64 + J) = r1;
            } else if (J < 128) {
                const int off = J - 64;
                *(__half2*)(g_kh + (size_t)pxa * 64 + off) = __floats2half2_rn(acc[mt][0] + b0, acc[mt][1] + b1);
                *(__half2*)(g_kh + (size_t)pxb * 64 + off) = __floats2half2_rn(acc[mt][2] + b0, acc[mt][3] + b1);
            } else {
                const int off = J - 128;
                *(__half2*)(g_vh + (size_t)pxa * 64 + off) = __floats2half2_rn(acc[mt][0] + b0, acc[mt][1] + b1);
                *(__half2*)(g_vh + (size_t)pxb * 64 + off) = __floats2half2_rn(acc[mt][2] + b0, acc[mt][3] + b1);
            }
        }
    }
}

// ---------------------------------------------------------------------------
// Kernel 2: attention, one head per block, THREE threads per query (192 thr).
// third = tid/64 handles 17/16/16 of the 49 window positions.
// ---------------------------------------------------------------------------
__global__ void __launch_bounds__(192) attn_kernel(const float* __restrict__ rpb) {
    extern __shared__ char smraw[];
    __half* ks = (__half*)smraw;                   // [196][APITCH]
    __half* vs = ks + NNB * APITCH;                // [196][APITCH]
    float*  rs = (float*)(vs + NNB * APITCH);      // [169] (pad 176)
    float*  pm = rs + 176;                         // [192]
    float*  ps = pm + 192;                         // [192]
    float*  os = ps + 192;                         // [2][64][33]

    const int tid  = threadIdx.x;
    const int half = tid / 64;                     // 0,1,2
    const int qid  = tid - half * 64;
    const int head = blockIdx.y;
    const int n    = blockIdx.z;
    const int x0   = (blockIdx.x >> 3) * 8;
    const int y0   = (blockIdx.x & 7) * 8;
    const int rb   = min(max(x0 - 3, 0), 50);
    const int cb   = min(max(y0 - 3, 0), 50);

    const int qx = qid >> 3, qy = qid & 7;
    const int xx = x0 + qx, yy = y0 + qy;
    const int hb = head * DHEAD;
    const int pix = n * 4096 + xx * 64 + yy;

    float q[32];
    {
        const float* qp = g_q + (size_t)pix * 64 + hb;
#pragma unroll
        for (int dq = 0; dq < 8; dq++) {
            const float4 t = *(const float4*)(qp + dq * 4);
            q[dq * 4 + 0] = t.x; q[dq * 4 + 1] = t.y;
            q[dq * 4 + 2] = t.z; q[dq * 4 + 3] = t.w;
        }
    }

    for (int i = tid; i < NNB * 8; i += 192) {
        const int nb = i >> 3, part = i & 7;
        const int gr = rb + nb / NBDIM, gc = cb + nb % NBDIM;
        const size_t psrc = (size_t)(n * 4096 + gr * 64 + gc) * 64 + hb;
        if (part < 4)
            *(uint4*)(ks + nb * APITCH + part * 8) = *(const uint4*)(g_kh + psrc + part * 8);
        else
            *(uint4*)(vs + nb * APITCH + (part - 4) * 8) = *(const uint4*)(g_vh + psrc + (part - 4) * 8);
    }
    for (int i = tid; i < 169; i += 192) rs[i] = rpb[head * 169 + i];
    __syncthreads();

    const int sx = min(max(xx - 3, 0), 57), sy = min(max(yy - 3, 0), 57);
    const int r0 = sx - rb, c0 = sy - cb;
    const int bh = sx - xx + 6, bw = sy - yy + 6;

    const int pbase = (half == 0) ? 0 : (1 + half * 16);   // 0,17,33
    const int pcnt  = (half == 0) ? 17 : 16;

    float lg[17];
    float m = -1e30f;
#pragma unroll
    for (int pp = 0; pp < 17; pp++) {
        if (pp < pcnt) {
            const int p = pbase + pp;
            const int a = p / 7, b = p % 7;
            const __half* kp = ks + ((r0 + a) * NBDIM + c0 + b) * APITCH;
            float a0 = 0.f, a1 = 0.f, a2 = 0.f, a3 = 0.f;
#pragma unroll
            for (int u = 0; u < 4; u++) {
                const uint4 r = *(const uint4*)(kp + u * 8);
                const float2 f0 = __half22float2(*(const __half2*)&r.x);
                const float2 f1 = __half22float2(*(const __half2*)&r.y);
                const float2 f2 = __half22float2(*(const __half2*)&r.z);
                const float2 f3 = __half22float2(*(const __half2*)&r.w);
                a0 += q[u * 8 + 0] * f0.x + q[u * 8 + 4] * f2.x;
                a1 += q[u * 8 + 1] * f0.y + q[u * 8 + 5] * f2.y;
                a2 += q[u * 8 + 2] * f1.x + q[u * 8 + 6] * f3.x;
                a3 += q[u * 8 + 3] * f1.y + q[u * 8 + 7] * f3.y;
            }
            lg[pp] = (a0 + a1) + (a2 + a3) + rs[(bh + a) * 13 + bw + b];
            m = fmaxf(m, lg[pp]);
        }
    }

    pm[tid] = m;
    __syncthreads();
    m = fmaxf(fmaxf(pm[qid], pm[qid + 64]), pm[qid + 128]);

    float s = 0.f;
#pragma unroll
    for (int pp = 0; pp < 17; pp++) {
        if (pp < pcnt) { const float e = __expf(lg[pp] - m); lg[pp] = e; s += e; }
    }
    ps[tid] = s;
    __syncthreads();
    const float inv = 1.0f / (ps[qid] + ps[qid + 64] + ps[qid + 128]);

    float o[32];
#pragma unroll
    for (int d = 0; d < 32; d++) o[d] = 0.f;
#pragma unroll
    for (int pp = 0; pp < 17; pp++) {
        if (pp < pcnt) {
            const int p = pbase + pp;
            const int a = p / 7, b = p % 7;
            const float w = lg[pp];
            const __half* vp = vs + ((r0 + a) * NBDIM + c0 + b) * APITCH;
#pragma unroll
            for (int u = 0; u < 4; u++) {
                const uint4 r = *(const uint4*)(vp + u * 8);
                const float2 f0 = __half22float2(*(const __half2*)&r.x);
                const float2 f1 = __half22float2(*(const __half2*)&r.y);
                const float2 f2 = __half22float2(*(const __half2*)&r.z);
                const float2 f3 = __half22float2(*(const __half2*)&r.w);
                o[u * 8 + 0] += w * f0.x; o[u * 8 + 1] += w * f0.y;
                o[u * 8 + 2] += w * f1.x; o[u * 8 + 3] += w * f1.y;
                o[u * 8 + 4] += w * f2.x; o[u * 8 + 5] += w * f2.y;
                o[u * 8 + 6] += w * f3.x; o[u * 8 + 7] += w * f3.y;
            }
        }
    }

    if (half > 0) {
        float* od = os + (size_t)(half - 1) * 64 * 33 + qid * 33;
#pragma unroll
        for (int d = 0; d < 32; d++) od[d] = o[d];
    }
    __syncthreads();
    if (half == 0) {
        const float* o1 = os + (size_t)qid * 33;
        const float* o2 = os + (size_t)64 * 33 + qid * 33;
        __align__(16) __half2 hh[16];
#pragma unroll
        for (int d2 = 0; d2 < 16; d2++) {
            const float v0 = (o[d2 * 2 + 0] + o1[d2 * 2 + 0] + o2[d2 * 2 + 0]) * inv;
            const float v1 = (o[d2 * 2 + 1] + o1[d2 * 2 + 1] + o2[d2 * 2 + 1]) * inv;
            hh[d2] = __floats2half2_rn(v0, v1);
        }
        uint4* dst = (uint4*)(g_atth + (size_t)pix * 64 + hb);
        const uint4* src = (const uint4*)hh;
        dst[0] = src[0]; dst[1] = src[1]; dst[2] = src[2]; dst[3] = src[3];
    }
}

// ---------------------------------------------------------------------------
// Kernel 3: proj on tensor cores, pure uint4 staging (g_atth + g_wph fp16).
// ---------------------------------------------------------------------------
__global__ void __launch_bounds__(256) proj_tc_kernel(const float* __restrict__ b_proj,
                                                      float* __restrict__ out, int out_size) {
    __shared__ __half xh[64 * XPITCH];   // [px][c]
    __shared__ __half wh[64 * XPITCH];   // [j][c]

    const int tid  = threadIdx.x;
    const int lane = tid & 31;
    const int warp = tid >> 5;
    const int pix0 = blockIdx.x * 64;

#pragma unroll
    for (int it = 0; it < 2; it++) {                 // x: 512 uint4 copies
        const int i = tid + it * 256;
        const int px = i >> 3, seg = i & 7;
        *(uint4*)&xh[px * XPITCH + seg * 8] = *(const uint4*)(g_atth + (size_t)(pix0 + px) * 64 + seg * 8);
    }
#pragma unroll
    for (int it = 0; it < 2; it++) {                 // w: 512 uint4 copies
        const int i = tid + it * 256;
        const int j = i >> 3, seg = i & 7;
        *(uint4*)&wh[j * XPITCH + seg * 8] = *(const uint4*)(g_wph + j * 64 + seg * 8);
    }
    __syncthreads();

    const unsigned xbase = (unsigned)__cvta_generic_to_shared(xh);
    const unsigned wbase = (unsigned)__cvta_generic_to_shared(wh);
    const int j0 = warp * 8;
    const int arow = lane & 15;
    const int acol8 = ((lane >> 4) & 1) * 8;
    const int l16 = lane & 15;

    float acc[4][4];
#pragma unroll
    for (int mt = 0; mt < 4; mt++)
#pragma unroll
        for (int r = 0; r < 4; r++) acc[mt][r] = 0.f;

#pragma unroll
    for (int ks = 0; ks < 4; ks++) {
        unsigned bfr[2];
        {
            const int brow = j0 + (l16 & 7);
            const int bcol = ks * 16 + ((l16 >> 3) & 1) * 8;
            ldsm2(bfr, wbase + (unsigned)(brow * XPITCH + bcol) * 2u);
        }
#pragma unroll
        for (int mt = 0; mt < 4; mt++) {
            unsigned afr[4];
            const int row = mt * 16 + arow;
            const int col = ks * 16 + acol8;
            ldsm4(afr, xbase + (unsigned)(row * XPITCH + col) * 2u);
            mma16816(acc[mt], afr, bfr);
        }
    }

    const int J = j0 + 2 * (lane & 3);
    const float b0 = b_proj[J], b1 = b_proj[J + 1];
#pragma unroll
    for (int mt = 0; mt < 4; mt++) {
        const int pxa = pix0 + mt * 16 + (lane >> 2);
        const int pxb = pxa + 8;
        *(float2*)(out + (size_t)pxa * 64 + J) = make_float2(acc[mt][0] + b0, acc[mt][1] + b1);
        *(float2*)(out + (size_t)pxb * 64 + J) = make_float2(acc[mt][2] + b0, acc[mt][3] + b1);
    }

    if (blockIdx.x == 0) {
        for (int i = NPIX * CCH + tid; i < out_size; i += 256) out[i] = 0.0f;
    }
}

// ---------------------------------------------------------------------------
extern "C" void kernel_launch(void* const* d_in, const int* in_sizes, int n_in,
                              void* d_out, int out_size) {
    const float* vid    = (const float*)d_in[0];
    const float* w_qkv  = (const float*)d_in[4];
    const float* b_qkv  = (const float*)d_in[5];
    const float* rpb    = (const float*)d_in[6];
    const float* w_proj = (const float*)d_in[7];
    const float* b_proj = (const float*)d_in[8];
    float* out = (float*)d_out;

    wprep_kernel<<<64, 256>>>(w_qkv, w_proj);
    qkv_tc_kernel<<<NPIX / 64, 256>>>(vid, b_qkv);

    const int attn_smem = 2 * NNB * APITCH * (int)sizeof(__half)
                        + (176 + 192 + 192 + 2 * 64 * 33) * (int)sizeof(float);  // ~49.3 KB
    cudaFuncSetAttribute(attn_kernel, cudaFuncAttributeMaxDynamicSharedMemorySize, attn_smem);
    attn_kernel<<<dim3(64, NHEADS, NIMG), 192, attn_smem>>>(rpb);

    proj_tc_kernel<<<NPIX / 64, 256>>>(b_proj, out, out_size);
}

// round 10
// speedup vs baseline: 1.7052x; 1.1166x over previous
#include <cuda_runtime.h>
#include <cuda_fp16.h>

// NATSearch: 2D neighborhood attention (NATTEN-style).
// wprep (fp16 w_qkv^T + w_proj^T) -> qkv GEMM TC -> FUSED attention+proj
// (both heads per block; proj TC GEMM on the in-smem att tile).

#define NIMG   4
#define HW     64
#define CCH    64
#define NHEADS 2
#define DHEAD  32
#define KWIN   7
#define NPIX   (NIMG * HW * HW)   // 16384
#define QKVD   192
#define NBDIM  14
#define NNB    (NBDIM * NBDIM)    // 196
#define FPITCH 72                 // halfs pitch (144B rows) for kv + mma tiles
#define QSCALE 0.17677669529663687f

__device__ __align__(16) __half g_wh [QKVD * CCH];  // [j][c] fp16 w_qkv^T
__device__ __align__(16) __half g_wph[CCH * CCH];   // [j][c] fp16 w_proj^T
__device__ __align__(16) float  g_q  [NPIX * CCH];  // [pix][64] fp32 (pre-scaled)
__device__ __align__(16) __half g_kh [NPIX * CCH];  // [pix][64] fp16
__device__ __align__(16) __half g_vh [NPIX * CCH];  // [pix][64] fp16

// ---------------------------------------------------------------------------
__device__ __forceinline__ void ldsm4(unsigned r[4], unsigned addr) {
    asm volatile("ldmatrix.sync.aligned.m8n8.x4.shared.b16 {%0,%1,%2,%3}, [%4];"
                 : "=r"(r[0]), "=r"(r[1]), "=r"(r[2]), "=r"(r[3]) : "r"(addr));
}
__device__ __forceinline__ void ldsm2(unsigned r[2], unsigned addr) {
    asm volatile("ldmatrix.sync.aligned.m8n8.x2.shared.b16 {%0,%1}, [%2];"
                 : "=r"(r[0]), "=r"(r[1]) : "r"(addr));
}
__device__ __forceinline__ void mma16816(float c[4], const unsigned a[4], const unsigned b[2]) {
    asm volatile(
        "mma.sync.aligned.m16n8k16.row.col.f32.f16.f16.f32 "
        "{%0,%1,%2,%3},{%4,%5,%6,%7},{%8,%9},{%0,%1,%2,%3};"
        : "+f"(c[0]), "+f"(c[1]), "+f"(c[2]), "+f"(c[3])
        : "r"(a[0]), "r"(a[1]), "r"(a[2]), "r"(a[3]), "r"(b[0]), "r"(b[1]));
}

// ---------------------------------------------------------------------------
// Kernel 0: weight prep. t<12288: w_qkv[c][j]->g_wh[j][c]. Rest: w_proj.
// ---------------------------------------------------------------------------
__global__ void __launch_bounds__(256) wprep_kernel(const float* __restrict__ w_qkv,
                                                    const float* __restrict__ w_proj) {
    const int t = blockIdx.x * 256 + threadIdx.x;      // 0..16383
    if (t < 64 * QKVD) {
        const int c = t / QKVD, j = t - c * QKVD;
        g_wh[j * 64 + c] = __float2half(w_qkv[t]);
    } else {
        const int t2 = t - 64 * QKVD;                  // 0..4095
        const int c = t2 >> 6, j = t2 & 63;
        g_wph[j * 64 + c] = __float2half(w_proj[t2]);
    }
}

// ---------------------------------------------------------------------------
// Kernel 1: qkv = x @ w_qkv + b_qkv (tensor cores). Unchanged from R9.
// ---------------------------------------------------------------------------
__global__ void __launch_bounds__(256) qkv_tc_kernel(const float* __restrict__ vid,
                                                     const float* __restrict__ b_qkv) {
    __shared__ __half xh[64 * FPITCH];    // [px][c]
    __shared__ __half wh[QKVD * FPITCH];  // [j][c]

    const int tid  = threadIdx.x;
    const int lane = tid & 31;
    const int warp = tid >> 5;
    const int pix0 = blockIdx.x * 64;
    const int n  = pix0 >> 12;
    const int xr = (pix0 >> 6) & 63;
    const float* vbase = vid + n * 262144 + xr * 64;

#pragma unroll
    for (int it = 0; it < 4; it++) {
        const int i = tid + it * 256;
        const int c = i >> 4, y4 = (i & 15) * 4;
        const float4 t = *(const float4*)(vbase + c * 4096 + y4);
        xh[(y4 + 0) * FPITCH + c] = __float2half(t.x);
        xh[(y4 + 1) * FPITCH + c] = __float2half(t.y);
        xh[(y4 + 2) * FPITCH + c] = __float2half(t.z);
        xh[(y4 + 3) * FPITCH + c] = __float2half(t.w);
    }
#pragma unroll
    for (int it = 0; it < 6; it++) {
        const int i = tid + it * 256;
        const int j = i >> 3, seg = i & 7;
        *(uint4*)&wh[j * FPITCH + seg * 8] = *(const uint4*)(g_wh + j * 64 + seg * 8);
    }
    __syncthreads();

    const unsigned xbase = (unsigned)__cvta_generic_to_shared(xh);
    const unsigned wbase = (unsigned)__cvta_generic_to_shared(wh);
    const int wn0 = warp * 24;
    const int arow = lane & 15;
    const int acol8 = ((lane >> 4) & 1) * 8;
    const int l16 = lane & 15;

#pragma unroll
    for (int nt = 0; nt < 3; nt++) {
        float acc[4][4];
#pragma unroll
        for (int mt = 0; mt < 4; mt++)
#pragma unroll
            for (int r = 0; r < 4; r++) acc[mt][r] = 0.f;

#pragma unroll
        for (int ks = 0; ks < 4; ks++) {
            unsigned bfr[2];
            {
                const int brow = wn0 + nt * 8 + (l16 & 7);
                const int bcol = ks * 16 + ((l16 >> 3) & 1) * 8;
                ldsm2(bfr, wbase + (unsigned)(brow * FPITCH + bcol) * 2u);
            }
#pragma unroll
            for (int mt = 0; mt < 4; mt++) {
                unsigned afr[4];
                const int row = mt * 16 + arow;
                const int col = ks * 16 + acol8;
                ldsm4(afr, xbase + (unsigned)(row * FPITCH + col) * 2u);
                mma16816(acc[mt], afr, bfr);
            }
        }

        const int J = wn0 + nt * 8 + 2 * (lane & 3);
        const float b0 = b_qkv[J], b1 = b_qkv[J + 1];
#pragma unroll
        for (int mt = 0; mt < 4; mt++) {
            const int pxa = pix0 + mt * 16 + (lane >> 2);
            const int pxb = pxa + 8;
            if (J < 64) {
                float2 r0 = make_float2((acc[mt][0] + b0) * QSCALE, (acc[mt][1] + b1) * QSCALE);
                float2 r1 = make_float2((acc[mt][2] + b0) * QSCALE, (acc[mt][3] + b1) * QSCALE);
                *(float2*)(g_q + (size_t)pxa * 64 + J) = r0;
                *(float2*)(g_q + (size_t)pxb * 64 + J) = r1;
            } else if (J < 128) {
                const int off = J - 64;
                *(__half2*)(g_kh + (size_t)pxa * 64 + off) = __floats2half2_rn(acc[mt][0] + b0, acc[mt][1] + b1);
                *(__half2*)(g_kh + (size_t)pxb * 64 + off) = __floats2half2_rn(acc[mt][2] + b0, acc[mt][3] + b1);
            } else {
                const int off = J - 128;
                *(__half2*)(g_vh + (size_t)pxa * 64 + off) = __floats2half2_rn(acc[mt][0] + b0, acc[mt][1] + b1);
                *(__half2*)(g_vh + (size_t)pxb * 64 + off) = __floats2half2_rn(acc[mt][2] + b0, acc[mt][3] + b1);
            }
        }
    }
}

// ---------------------------------------------------------------------------
// Kernel 2: FUSED attention + proj. Block = 8x8 query tile, BOTH heads,
// 256 thr = 64 q x 2 heads x 2 position-halves. After softmax/AV, the
// 64px x 64ch att tile lives in smem -> proj via tensor cores in-block.
// smem: [ks | vs | rs | pm | ps | atts | wps], os aliased over ks.
// ---------------------------------------------------------------------------
#define OFF_KS   0
#define OFF_VS   (NNB * FPITCH * 2)                    // 28224
#define OFF_RS   (OFF_VS + NNB * FPITCH * 2)           // 56448
#define OFF_PM   (OFF_RS + 344 * 4)                    // rs: 338 floats pad 344
#define OFF_PS   (OFF_PM + 256 * 4)
#define OFF_ATTS (OFF_PS + 256 * 4)
#define OFF_WPS  (OFF_ATTS + 64 * FPITCH * 2)
#define SMEM_FUSED (OFF_WPS + 64 * FPITCH * 2)

__global__ void __launch_bounds__(256) attnproj_kernel(const float* __restrict__ rpb,
                                                       const float* __restrict__ b_proj,
                                                       float* __restrict__ out, int out_size) {
    extern __shared__ char smraw[];
    __half* ks   = (__half*)(smraw + OFF_KS);      // [196][FPITCH]
    __half* vs   = (__half*)(smraw + OFF_VS);      // [196][FPITCH]
    float*  rs   = (float*) (smraw + OFF_RS);      // [2][169]
    float*  pm   = (float*) (smraw + OFF_PM);      // [256]
    float*  ps   = (float*) (smraw + OFF_PS);      // [256]
    __half* atts = (__half*)(smraw + OFF_ATTS);    // [64][FPITCH]
    __half* wps  = (__half*)(smraw + OFF_WPS);     // [64][FPITCH]
    float*  os   = (float*) (smraw + OFF_KS);      // [2][64][33] aliases ks (dead after logits)

    const int tid  = threadIdx.x;
    const int lane = tid & 31;
    const int warp = tid >> 5;
    const int qid  = tid & 63;
    const int head = (tid >> 6) & 1;
    const int half = tid >> 7;
    const int n    = blockIdx.y;
    const int x0   = (blockIdx.x >> 3) * 8;
    const int y0   = (blockIdx.x & 7) * 8;
    const int rb   = min(max(x0 - 3, 0), 50);
    const int cb   = min(max(y0 - 3, 0), 50);

    const int qx = qid >> 3, qy = qid & 7;
    const int xx = x0 + qx, yy = y0 + qy;
    const int hb = head * DHEAD;
    const int pix = n * 4096 + xx * 64 + yy;

    // q (this head), global load overlaps staging
    float q[32];
    {
        const float* qp = g_q + (size_t)pix * 64 + hb;
#pragma unroll
        for (int dq = 0; dq < 8; dq++) {
            const float4 t = *(const float4*)(qp + dq * 4);
            q[dq * 4 + 0] = t.x; q[dq * 4 + 1] = t.y;
            q[dq * 4 + 2] = t.z; q[dq * 4 + 3] = t.w;
        }
    }

    // stage k/v (BOTH heads, full 64 ch): 196 x 16 uint4
    for (int i = tid; i < NNB * 16; i += 256) {
        const int nb = i >> 4, part = i & 15;
        const int gr = rb + nb / NBDIM, gc = cb + nb % NBDIM;
        const size_t psrc = (size_t)(n * 4096 + gr * 64 + gc) * 64;
        if (part < 8)
            *(uint4*)(ks + nb * FPITCH + part * 8) = *(const uint4*)(g_kh + psrc + part * 8);
        else
            *(uint4*)(vs + nb * FPITCH + (part - 8) * 8) = *(const uint4*)(g_vh + psrc + (part - 8) * 8);
    }
    for (int i = tid; i < 2 * 169; i += 256) rs[i] = rpb[i];
    // stage w_proj for the fused proj GEMM
#pragma unroll
    for (int it = 0; it < 2; it++) {
        const int i = tid + it * 256;
        const int j = i >> 3, seg = i & 7;
        *(uint4*)&wps[j * FPITCH + seg * 8] = *(const uint4*)(g_wph + j * 64 + seg * 8);
    }
    __syncthreads();

    const int sx = min(max(xx - 3, 0), 57), sy = min(max(yy - 3, 0), 57);
    const int r0 = sx - rb, c0 = sy - cb;
    const int bh = sx - xx + 6, bw = sy - yy + 6;
    const float* rh = rs + head * 169;

    const int pbase = half * 25;
    const int pcnt  = 25 - half;        // 25 / 24

    float lg[25];
    float m = -1e30f;
#pragma unroll
    for (int pp = 0; pp < 25; pp++) {
        if (pp < pcnt) {
            const int p = pbase + pp;
            const int a = p / 7, b = p % 7;
            const __half* kp = ks + ((r0 + a) * NBDIM + c0 + b) * FPITCH + hb;
            float a0 = 0.f, a1 = 0.f, a2 = 0.f, a3 = 0.f;
#pragma unroll
            for (int u = 0; u < 4; u++) {
                const uint4 r = *(const uint4*)(kp + u * 8);
                const float2 f0 = __half22float2(*(const __half2*)&r.x);
                const float2 f1 = __half22float2(*(const __half2*)&r.y);
                const float2 f2 = __half22float2(*(const __half2*)&r.z);
                const float2 f3 = __half22float2(*(const __half2*)&r.w);
                a0 += q[u * 8 + 0] * f0.x + q[u * 8 + 4] * f2.x;
                a1 += q[u * 8 + 1] * f0.y + q[u * 8 + 5] * f2.y;
                a2 += q[u * 8 + 2] * f1.x + q[u * 8 + 6] * f3.x;
                a3 += q[u * 8 + 3] * f1.y + q[u * 8 + 7] * f3.y;
            }
            lg[pp] = (a0 + a1) + (a2 + a3) + rh[(bh + a) * 13 + bw + b];
            m = fmaxf(m, lg[pp]);
        }
    }

    pm[tid] = m;
    __syncthreads();                    // also: last read of ks above -> os alias safe after
    m = fmaxf(pm[tid & 127], pm[(tid & 127) + 128]);

    float s = 0.f;
#pragma unroll
    for (int pp = 0; pp < 25; pp++) {
        if (pp < pcnt) { const float e = __expf(lg[pp] - m); lg[pp] = e; s += e; }
    }
    ps[tid] = s;
    __syncthreads();
    const float inv = 1.0f / (ps[tid & 127] + ps[(tid & 127) + 128]);

    float o[32];
#pragma unroll
    for (int d = 0; d < 32; d++) o[d] = 0.f;
#pragma unroll
    for (int pp = 0; pp < 25; pp++) {
        if (pp < pcnt) {
            const int p = pbase + pp;
            const int a = p / 7, b = p % 7;
            const float w = lg[pp];
            const __half* vp = vs + ((r0 + a) * NBDIM + c0 + b) * FPITCH + hb;
#pragma unroll
            for (int u = 0; u < 4; u++) {
                const uint4 r = *(const uint4*)(vp + u * 8);
                const float2 f0 = __half22float2(*(const __half2*)&r.x);
                const float2 f1 = __half22float2(*(const __half2*)&r.y);
                const float2 f2 = __half22float2(*(const __half2*)&r.z);
                const float2 f3 = __half22float2(*(const __half2*)&r.w);
                o[u * 8 + 0] += w * f0.x; o[u * 8 + 1] += w * f0.y;
                o[u * 8 + 2] += w * f1.x; o[u * 8 + 3] += w * f1.y;
                o[u * 8 + 4] += w * f2.x; o[u * 8 + 5] += w * f2.y;
                o[u * 8 + 6] += w * f3.x; o[u * 8 + 7] += w * f3.y;
            }
        }
    }

    // combine halves -> att tile [qid][64ch] fp16 in smem
    if (half == 1) {
        float* od = os + (size_t)(head * 64 + qid) * 33;
#pragma unroll
        for (int d = 0; d < 32; d++) od[d] = o[d];
    }
    __syncthreads();
    if (half == 0) {
        const float* o1 = os + (size_t)(head * 64 + qid) * 33;
        __align__(16) __half2 hh[16];
#pragma unroll
        for (int d2 = 0; d2 < 16; d2++) {
            hh[d2] = __floats2half2_rn((o[d2 * 2 + 0] + o1[d2 * 2 + 0]) * inv,
                                       (o[d2 * 2 + 1] + o1[d2 * 2 + 1]) * inv);
        }
        uint4* dst = (uint4*)(atts + qid * FPITCH + hb);
        const uint4* src = (const uint4*)hh;
        dst[0] = src[0]; dst[1] = src[1]; dst[2] = src[2]; dst[3] = src[3];
    }
    __syncthreads();

    // ---- fused proj: out[64px x 64j] = atts @ wps^T + b_proj ----
    const unsigned abase = (unsigned)__cvta_generic_to_shared(atts);
    const unsigned wbase = (unsigned)__cvta_generic_to_shared(wps);
    const int j0 = warp * 8;
    const int arow = lane & 15;
    const int acol8 = ((lane >> 4) & 1) * 8;
    const int l16 = lane & 15;

    float acc[4][4];
#pragma unroll
    for (int mt = 0; mt < 4; mt++)
#pragma unroll
        for (int r = 0; r < 4; r++) acc[mt][r] = 0.f;

#pragma unroll
    for (int kk = 0; kk < 4; kk++) {
        unsigned bfr[2];
        {
            const int brow = j0 + (l16 & 7);
            const int bcol = kk * 16 + ((l16 >> 3) & 1) * 8;
            ldsm2(bfr, wbase + (unsigned)(brow * FPITCH + bcol) * 2u);
        }
#pragma unroll
        for (int mt = 0; mt < 4; mt++) {
            unsigned afr[4];
            const int row = mt * 16 + arow;
            const int col = kk * 16 + acol8;
            ldsm4(afr, abase + (unsigned)(row * FPITCH + col) * 2u);
            mma16816(acc[mt], afr, bfr);
        }
    }

    const int J = j0 + 2 * (lane & 3);
    const float b0 = b_proj[J], b1 = b_proj[J + 1];
#pragma unroll
    for (int mt = 0; mt < 4; mt++) {
#pragma unroll
        for (int rr = 0; rr < 2; rr++) {
            const int row = mt * 16 + (lane >> 2) + rr * 8;   // qid index
            const int opix = n * 4096 + (x0 + (row >> 3)) * 64 + (y0 + (row & 7));
            *(float2*)(out + (size_t)opix * 64 + J) =
                make_float2(acc[mt][rr * 2 + 0] + b0, acc[mt][rr * 2 + 1] + b1);
        }
    }

    if (blockIdx.x == 0 && blockIdx.y == 0) {
        for (int i = NPIX * CCH + tid; i < out_size; i += 256) out[i] = 0.0f;
    }
}

// ---------------------------------------------------------------------------
extern "C" void kernel_launch(void* const* d_in, const int* in_sizes, int n_in,
                              void* d_out, int out_size) {
    const float* vid    = (const float*)d_in[0];
    const float* w_qkv  = (const float*)d_in[4];
    const float* b_qkv  = (const float*)d_in[5];
    const float* rpb    = (const float*)d_in[6];
    const float* w_proj = (const float*)d_in[7];
    const float* b_proj = (const float*)d_in[8];
    float* out = (float*)d_out;

    wprep_kernel<<<64, 256>>>(w_qkv, w_proj);
    qkv_tc_kernel<<<NPIX / 64, 256>>>(vid, b_qkv);

    cudaFuncSetAttribute(attnproj_kernel, cudaFuncAttributeMaxDynamicSharedMemorySize, SMEM_FUSED);
    attnproj_kernel<<<dim3(64, NIMG), 256, SMEM_FUSED>>>(rpb, b_proj, out, out_size);
}

// round 11
// speedup vs baseline: 1.7942x; 1.0522x over previous
#include <cuda_runtime.h>
#include <cuda_fp16.h>

// NATSearch: 2D neighborhood attention (NATTEN-style). TWO launches:
// qkv GEMM TC (weights converted in-block, natural [c][j] layout + trans-ldmatrix)
// -> FUSED attention+proj (both heads; proj TC GEMM on in-smem att tile).

#define NIMG   4
#define HW     64
#define CCH    64
#define NHEADS 2
#define DHEAD  32
#define KWIN   7
#define NPIX   (NIMG * HW * HW)   // 16384
#define QKVD   192
#define NBDIM  14
#define NNB    (NBDIM * NBDIM)    // 196
#define FPITCH 72                 // halfs pitch (144B rows)
#define WPITCH 200                // halfs pitch for [c][192] w tile (400B rows)
#define QSCALE 0.17677669529663687f

__device__ __align__(16) float  g_q [NPIX * CCH];   // [pix][64] fp32 (pre-scaled)
__device__ __align__(16) __half g_kh[NPIX * CCH];   // [pix][64] fp16
__device__ __align__(16) __half g_vh[NPIX * CCH];   // [pix][64] fp16

// ---------------------------------------------------------------------------
__device__ __forceinline__ void ldsm4(unsigned r[4], unsigned addr) {
    asm volatile("ldmatrix.sync.aligned.m8n8.x4.shared.b16 {%0,%1,%2,%3}, [%4];"
                 : "=r"(r[0]), "=r"(r[1]), "=r"(r[2]), "=r"(r[3]) : "r"(addr));
}
__device__ __forceinline__ void ldsm2t(unsigned r[2], unsigned addr) {
    asm volatile("ldmatrix.sync.aligned.m8n8.x2.trans.shared.b16 {%0,%1}, [%2];"
                 : "=r"(r[0]), "=r"(r[1]) : "r"(addr));
}
__device__ __forceinline__ void mma16816(float c[4], const unsigned a[4], const unsigned b[2]) {
    asm volatile(
        "mma.sync.aligned.m16n8k16.row.col.f32.f16.f16.f32 "
        "{%0,%1,%2,%3},{%4,%5,%6,%7},{%8,%9},{%0,%1,%2,%3};"
        : "+f"(c[0]), "+f"(c[1]), "+f"(c[2]), "+f"(c[3])
        : "r"(a[0]), "r"(a[1]), "r"(a[2]), "r"(a[3]), "r"(b[0]), "r"(b[1]));
}

// ---------------------------------------------------------------------------
// Kernel 1: qkv = x @ w_qkv + b_qkv (tensor cores). 256 thr / 8 warps,
// tile 64 px x 192 cols. w converted in-block to fp16 NATURAL [c][j] layout;
// B fragments via ldmatrix.trans (rows = c = k-dim).
// ---------------------------------------------------------------------------
__global__ void __launch_bounds__(256) qkv_tc_kernel(const float* __restrict__ vid,
                                                     const float* __restrict__ w_qkv,
                                                     const float* __restrict__ b_qkv) {
    __shared__ __half xh[64 * FPITCH];    // [px][c]
    __shared__ __half wc[64 * WPITCH];    // [c][j] natural layout

    const int tid  = threadIdx.x;
    const int lane = tid & 31;
    const int warp = tid >> 5;
    const int pix0 = blockIdx.x * 64;
    const int n  = pix0 >> 12;
    const int xr = (pix0 >> 6) & 63;
    const float* vbase = vid + n * 262144 + xr * 64;

#pragma unroll
    for (int it = 0; it < 4; it++) {                // x: float4 load + transpose-convert
        const int i = tid + it * 256;               // 0..1023
        const int c = i >> 4, y4 = (i & 15) * 4;
        const float4 t = *(const float4*)(vbase + c * 4096 + y4);
        xh[(y4 + 0) * FPITCH + c] = __float2half(t.x);
        xh[(y4 + 1) * FPITCH + c] = __float2half(t.y);
        xh[(y4 + 2) * FPITCH + c] = __float2half(t.z);
        xh[(y4 + 3) * FPITCH + c] = __float2half(t.w);
    }
#pragma unroll
    for (int it = 0; it < 12; it++) {               // w: coalesced convert, no transpose
        const int i = tid + it * 256;               // 0..3071
        const int c = i / 48, jq = i % 48;
        const float4 t = *(const float4*)(w_qkv + c * QKVD + jq * 4);
        __half2 h0 = __floats2half2_rn(t.x, t.y);
        __half2 h1 = __floats2half2_rn(t.z, t.w);
        uint2 u; u.x = *(unsigned*)&h0; u.y = *(unsigned*)&h1;
        *(uint2*)&wc[c * WPITCH + jq * 4] = u;
    }
    __syncthreads();

    const unsigned xbase = (unsigned)__cvta_generic_to_shared(xh);
    const unsigned wbase = (unsigned)__cvta_generic_to_shared(wc);
    const int wn0 = warp * 24;
    const int arow = lane & 15;
    const int acol8 = ((lane >> 4) & 1) * 8;
    const int l16 = lane & 15;

#pragma unroll
    for (int nt = 0; nt < 3; nt++) {
        float acc[4][4];
#pragma unroll
        for (int mt = 0; mt < 4; mt++)
#pragma unroll
            for (int r = 0; r < 4; r++) acc[mt][r] = 0.f;

#pragma unroll
        for (int ks = 0; ks < 4; ks++) {
            unsigned bfr[2];
            // B[k=c][n=j] row-major -> trans load: row k0+l16, col wn0+nt*8
            ldsm2t(bfr, wbase + (unsigned)((ks * 16 + l16) * WPITCH + wn0 + nt * 8) * 2u);
#pragma unroll
            for (int mt = 0; mt < 4; mt++) {
                unsigned afr[4];
                const int row = mt * 16 + arow;
                const int col = ks * 16 + acol8;
                ldsm4(afr, xbase + (unsigned)(row * FPITCH + col) * 2u);
                mma16816(acc[mt], afr, bfr);
            }
        }

        const int J = wn0 + nt * 8 + 2 * (lane & 3);
        const float b0 = b_qkv[J], b1 = b_qkv[J + 1];
#pragma unroll
        for (int mt = 0; mt < 4; mt++) {
            const int pxa = pix0 + mt * 16 + (lane >> 2);
            const int pxb = pxa + 8;
            if (J < 64) {
                float2 r0 = make_float2((acc[mt][0] + b0) * QSCALE, (acc[mt][1] + b1) * QSCALE);
                float2 r1 = make_float2((acc[mt][2] + b0) * QSCALE, (acc[mt][3] + b1) * QSCALE);
                *(float2*)(g_q + (size_t)pxa * 64 + J) = r0;
                *(float2*)(g_q + (size_t)pxb * 64 + J) = r1;
            } else if (J < 128) {
                const int off = J - 64;
                *(__half2*)(g_kh + (size_t)pxa * 64 + off) = __floats2half2_rn(acc[mt][0] + b0, acc[mt][1] + b1);
                *(__half2*)(g_kh + (size_t)pxb * 64 + off) = __floats2half2_rn(acc[mt][2] + b0, acc[mt][3] + b1);
            } else {
                const int off = J - 128;
                *(__half2*)(g_vh + (size_t)pxa * 64 + off) = __floats2half2_rn(acc[mt][0] + b0, acc[mt][1] + b1);
                *(__half2*)(g_vh + (size_t)pxb * 64 + off) = __floats2half2_rn(acc[mt][2] + b0, acc[mt][3] + b1);
            }
        }
    }
}

// ---------------------------------------------------------------------------
// Kernel 2: FUSED attention + proj. Block = 8x8 query tile, BOTH heads,
// 256 thr = 64 q x 2 heads x 2 position-halves. w_proj converted in-block
// (natural [c][j] layout, trans-ldmatrix B). os aliased over ks.
// ---------------------------------------------------------------------------
#define OFF_KS   0
#define OFF_VS   (NNB * FPITCH * 2)                    // 28224
#define OFF_RS   (OFF_VS + NNB * FPITCH * 2)           // 56448
#define OFF_PM   (OFF_RS + 344 * 4)                    // rs: 338 floats pad 344
#define OFF_PS   (OFF_PM + 256 * 4)
#define OFF_ATTS (OFF_PS + 256 * 4)
#define OFF_WPS  (OFF_ATTS + 64 * FPITCH * 2)
#define SMEM_FUSED (OFF_WPS + 64 * FPITCH * 2)

__global__ void __launch_bounds__(256) attnproj_kernel(const float* __restrict__ rpb,
                                                       const float* __restrict__ w_proj,
                                                       const float* __restrict__ b_proj,
                                                       float* __restrict__ out, int out_size) {
    extern __shared__ char smraw[];
    __half* ks   = (__half*)(smraw + OFF_KS);      // [196][FPITCH]
    __half* vs   = (__half*)(smraw + OFF_VS);      // [196][FPITCH]
    float*  rs   = (float*) (smraw + OFF_RS);      // [2][169]
    float*  pm   = (float*) (smraw + OFF_PM);      // [256]
    float*  ps   = (float*) (smraw + OFF_PS);      // [256]
    __half* atts = (__half*)(smraw + OFF_ATTS);    // [64][FPITCH]
    __half* wps  = (__half*)(smraw + OFF_WPS);     // [c][j] natural, pitch FPITCH
    float*  os   = (float*) (smraw + OFF_KS);      // [2][64][33] aliases ks

    const int tid  = threadIdx.x;
    const int lane = tid & 31;
    const int warp = tid >> 5;
    const int qid  = tid & 63;
    const int head = (tid >> 6) & 1;
    const int half = tid >> 7;
    const int n    = blockIdx.y;
    const int x0   = (blockIdx.x >> 3) * 8;
    const int y0   = (blockIdx.x & 7) * 8;
    const int rb   = min(max(x0 - 3, 0), 50);
    const int cb   = min(max(y0 - 3, 0), 50);

    const int qx = qid >> 3, qy = qid & 7;
    const int xx = x0 + qx, yy = y0 + qy;
    const int hb = head * DHEAD;
    const int pix = n * 4096 + xx * 64 + yy;

    float q[32];
    {
        const float* qp = g_q + (size_t)pix * 64 + hb;
#pragma unroll
        for (int dq = 0; dq < 8; dq++) {
            const float4 t = *(const float4*)(qp + dq * 4);
            q[dq * 4 + 0] = t.x; q[dq * 4 + 1] = t.y;
            q[dq * 4 + 2] = t.z; q[dq * 4 + 3] = t.w;
        }
    }

    // stage k/v (BOTH heads, full 64 ch): 196 x 16 uint4
    for (int i = tid; i < NNB * 16; i += 256) {
        const int nb = i >> 4, part = i & 15;
        const int gr = rb + nb / NBDIM, gc = cb + nb % NBDIM;
        const size_t psrc = (size_t)(n * 4096 + gr * 64 + gc) * 64;
        if (part < 8)
            *(uint4*)(ks + nb * FPITCH + part * 8) = *(const uint4*)(g_kh + psrc + part * 8);
        else
            *(uint4*)(vs + nb * FPITCH + (part - 8) * 8) = *(const uint4*)(g_vh + psrc + (part - 8) * 8);
    }
    for (int i = tid; i < 2 * 169; i += 256) rs[i] = rpb[i];
    // stage w_proj: coalesced convert, natural [c][j]
#pragma unroll
    for (int it = 0; it < 4; it++) {
        const int i = tid + it * 256;               // 0..1023
        const int c = i >> 4, jq = i & 15;
        const float4 t = *(const float4*)(w_proj + c * 64 + jq * 4);
        __half2 h0 = __floats2half2_rn(t.x, t.y);
        __half2 h1 = __floats2half2_rn(t.z, t.w);
        uint2 u; u.x = *(unsigned*)&h0; u.y = *(unsigned*)&h1;
        *(uint2*)&wps[c * FPITCH + jq * 4] = u;
    }
    __syncthreads();

    const int sx = min(max(xx - 3, 0), 57), sy = min(max(yy - 3, 0), 57);
    const int r0 = sx - rb, c0 = sy - cb;
    const int bh = sx - xx + 6, bw = sy - yy + 6;
    const float* rh = rs + head * 169;

    const int pbase = half * 25;
    const int pcnt  = 25 - half;        // 25 / 24

    float lg[25];
    float m = -1e30f;
#pragma unroll
    for (int pp = 0; pp < 25; pp++) {
        if (pp < pcnt) {
            const int p = pbase + pp;
            const int a = p / 7, b = p % 7;
            const __half* kp = ks + ((r0 + a) * NBDIM + c0 + b) * FPITCH + hb;
            float a0 = 0.f, a1 = 0.f, a2 = 0.f, a3 = 0.f;
#pragma unroll
            for (int u = 0; u < 4; u++) {
                const uint4 r = *(const uint4*)(kp + u * 8);
                const float2 f0 = __half22float2(*(const __half2*)&r.x);
                const float2 f1 = __half22float2(*(const __half2*)&r.y);
                const float2 f2 = __half22float2(*(const __half2*)&r.z);
                const float2 f3 = __half22float2(*(const __half2*)&r.w);
                a0 += q[u * 8 + 0] * f0.x + q[u * 8 + 4] * f2.x;
                a1 += q[u * 8 + 1] * f0.y + q[u * 8 + 5] * f2.y;
                a2 += q[u * 8 + 2] * f1.x + q[u * 8 + 6] * f3.x;
                a3 += q[u * 8 + 3] * f1.y + q[u * 8 + 7] * f3.y;
            }
            lg[pp] = (a0 + a1) + (a2 + a3) + rh[(bh + a) * 13 + bw + b];
            m = fmaxf(m, lg[pp]);
        }
    }

    pm[tid] = m;
    __syncthreads();
    m = fmaxf(pm[tid & 127], pm[(tid & 127) + 128]);

    float s = 0.f;
#pragma unroll
    for (int pp = 0; pp < 25; pp++) {
        if (pp < pcnt) { const float e = __expf(lg[pp] - m); lg[pp] = e; s += e; }
    }
    ps[tid] = s;
    __syncthreads();
    const float inv = 1.0f / (ps[tid & 127] + ps[(tid & 127) + 128]);

    float o[32];
#pragma unroll
    for (int d = 0; d < 32; d++) o[d] = 0.f;
#pragma unroll
    for (int pp = 0; pp < 25; pp++) {
        if (pp < pcnt) {
            const int p = pbase + pp;
            const int a = p / 7, b = p % 7;
            const float w = lg[pp];
            const __half* vp = vs + ((r0 + a) * NBDIM + c0 + b) * FPITCH + hb;
#pragma unroll
            for (int u = 0; u < 4; u++) {
                const uint4 r = *(const uint4*)(vp + u * 8);
                const float2 f0 = __half22float2(*(const __half2*)&r.x);
                const float2 f1 = __half22float2(*(const __half2*)&r.y);
                const float2 f2 = __half22float2(*(const __half2*)&r.z);
                const float2 f3 = __half22float2(*(const __half2*)&r.w);
                o[u * 8 + 0] += w * f0.x; o[u * 8 + 1] += w * f0.y;
                o[u * 8 + 2] += w * f1.x; o[u * 8 + 3] += w * f1.y;
                o[u * 8 + 4] += w * f2.x; o[u * 8 + 5] += w * f2.y;
                o[u * 8 + 6] += w * f3.x; o[u * 8 + 7] += w * f3.y;
            }
        }
    }

    // combine halves -> att tile [qid][64ch] fp16 in smem
    if (half == 1) {
        float* od = os + (size_t)(head * 64 + qid) * 33;
#pragma unroll
        for (int d = 0; d < 32; d++) od[d] = o[d];
    }
    __syncthreads();
    if (half == 0) {
        const float* o1 = os + (size_t)(head * 64 + qid) * 33;
        __align__(16) __half2 hh[16];
#pragma unroll
        for (int d2 = 0; d2 < 16; d2++) {
            hh[d2] = __floats2half2_rn((o[d2 * 2 + 0] + o1[d2 * 2 + 0]) * inv,
                                       (o[d2 * 2 + 1] + o1[d2 * 2 + 1]) * inv);
        }
        uint4* dst = (uint4*)(atts + qid * FPITCH + hb);
        const uint4* src = (const uint4*)hh;
        dst[0] = src[0]; dst[1] = src[1]; dst[2] = src[2]; dst[3] = src[3];
    }
    __syncthreads();

    // ---- fused proj: out[64px x 64j] = atts @ w_proj + b_proj ----
    const unsigned abase = (unsigned)__cvta_generic_to_shared(atts);
    const unsigned wbase = (unsigned)__cvta_generic_to_shared(wps);
    const int j0 = warp * 8;
    const int arow = lane & 15;
    const int acol8 = ((lane >> 4) & 1) * 8;
    const int l16 = lane & 15;

    float acc[4][4];
#pragma unroll
    for (int mt = 0; mt < 4; mt++)
#pragma unroll
        for (int r = 0; r < 4; r++) acc[mt][r] = 0.f;

#pragma unroll
    for (int kk = 0; kk < 4; kk++) {
        unsigned bfr[2];
        // B[k=c][n=j] row-major -> trans load: row kk*16+l16, col j0
        ldsm2t(bfr, wbase + (unsigned)((kk * 16 + l16) * FPITCH + j0) * 2u);
#pragma unroll
        for (int mt = 0; mt < 4; mt++) {
            unsigned afr[4];
            const int row = mt * 16 + arow;
            const int col = kk * 16 + acol8;
            ldsm4(afr, abase + (unsigned)(row * FPITCH + col) * 2u);
            mma16816(acc[mt], afr, bfr);
        }
    }

    const int J = j0 + 2 * (lane & 3);
    const float b0 = b_proj[J], b1 = b_proj[J + 1];
#pragma unroll
    for (int mt = 0; mt < 4; mt++) {
#pragma unroll
        for (int rr = 0; rr < 2; rr++) {
            const int row = mt * 16 + (lane >> 2) + rr * 8;   // qid index
            const int opix = n * 4096 + (x0 + (row >> 3)) * 64 + (y0 + (row & 7));
            *(float2*)(out + (size_t)opix * 64 + J) =
                make_float2(acc[mt][rr * 2 + 0] + b0, acc[mt][rr * 2 + 1] + b1);
        }
    }

    if (blockIdx.x == 0 && blockIdx.y == 0) {
        for (int i = NPIX * CCH + tid; i < out_size; i += 256) out[i] = 0.0f;
    }
}

// ---------------------------------------------------------------------------
extern "C" void kernel_launch(void* const* d_in, const int* in_sizes, int n_in,
                              void* d_out, int out_size) {
    const float* vid    = (const float*)d_in[0];
    const float* w_qkv  = (const float*)d_in[4];
    const float* b_qkv  = (const float*)d_in[5];
    const float* rpb    = (const float*)d_in[6];
    const float* w_proj = (const float*)d_in[7];
    const float* b_proj = (const float*)d_in[8];
    float* out = (float*)d_out;

    qkv_tc_kernel<<<NPIX / 64, 256>>>(vid, w_qkv, b_qkv);

    cudaFuncSetAttribute(attnproj_kernel, cudaFuncAttributeMaxDynamicSharedMemorySize, SMEM_FUSED);
    attnproj_kernel<<<dim3(64, NIMG), 256, SMEM_FUSED>>>(rpb, w_proj, b_proj, out, out_size);
}